// round 1
// baseline (speedup 1.0000x reference)
#include <cuda_runtime.h>
#include <cuda_bf16.h>
#include <stdint.h>

// Problem constants
#define Nn    100000
#define INCH  256
#define HIDC  128
#define OUTC  64
#define Ee    1600000
#define EPp   500000

// ---------------------------------------------------------------------------
// Scratch (no allocations allowed -> __device__ globals)
// ---------------------------------------------------------------------------
__device__ float g_Hlin[(size_t)Nn * HIDC];   // x @ W1
__device__ float g_Hagg[(size_t)Nn * HIDC];   // relu(gcn1)
__device__ float g_H2lin[(size_t)Nn * OUTC];  // Hagg @ W2
__device__ float g_Z[(size_t)Nn * OUTC];      // gcn2 output
__device__ float g_dinv[Nn];
__device__ int   g_deg[Nn];
__device__ int   g_rowstart[Nn + 1];
__device__ int   g_cursor[Nn];
__device__ int   g_csr_src[Ee];
__device__ int   g_is64;

// ---------------------------------------------------------------------------
// Index helper: edge tensors may be int32 or int64 depending on jax x64 mode.
// ---------------------------------------------------------------------------
__device__ __forceinline__ int ld_idx(const void* p, int i, int is64) {
    if (is64) return (int)((const long long*)p)[i];
    return ((const int*)p)[i];
}

// Detect int64 vs int32: for int64 little-endian values < 2^31 every odd
// 32-bit word is zero. For int32 random indices in [0,100000) this is
// impossible over 2048 samples. Deterministic for fixed inputs.
__global__ void k_detect(const int* __restrict__ p) {
    __shared__ int any;
    if (threadIdx.x == 0) any = 0;
    __syncthreads();
    for (int i = threadIdx.x; i < 2048; i += blockDim.x)
        if (p[2 * i + 1] != 0) any = 1;
    __syncthreads();
    if (threadIdx.x == 0) g_is64 = any ? 0 : 1;
}

__global__ void k_zero_deg() {
    int i = blockIdx.x * blockDim.x + threadIdx.x;
    if (i < Nn) g_deg[i] = 0;
}

__global__ void k_count(const void* __restrict__ edge) {
    int e = blockIdx.x * blockDim.x + threadIdx.x;
    if (e >= Ee) return;
    const int is64 = g_is64;
    int dst = ld_idx(edge, Ee + e, is64);
    atomicAdd(&g_deg[dst], 1);
}

// Single-block exclusive scan over deg -> rowstart, cursor. rowstart[N] = E.
__global__ void k_scan() {
    const int T = 1024;
    __shared__ int ssum[T];
    int t = threadIdx.x;
    const int chunk = (Nn + T - 1) / T;
    int begin = t * chunk;
    int end = begin + chunk; if (end > Nn) end = Nn;
    if (begin > Nn) begin = Nn;
    int sum = 0;
    for (int i = begin; i < end; i++) sum += g_deg[i];
    ssum[t] = sum;
    __syncthreads();
    // inclusive Hillis-Steele
    for (int off = 1; off < T; off <<= 1) {
        int v = 0;
        if (t >= off) v = ssum[t - off];
        __syncthreads();
        if (t >= off) ssum[t] += v;
        __syncthreads();
    }
    int run = (t == 0) ? 0 : ssum[t - 1];
    for (int i = begin; i < end; i++) {
        g_rowstart[i] = run;
        g_cursor[i] = run;
        run += g_deg[i];
    }
    if (t == T - 1) g_rowstart[Nn] = ssum[T - 1];
}

__global__ void k_fill(const void* __restrict__ edge) {
    int e = blockIdx.x * blockDim.x + threadIdx.x;
    if (e >= Ee) return;
    const int is64 = g_is64;
    int src = ld_idx(edge, e, is64);
    int dst = ld_idx(edge, Ee + e, is64);
    int pos = atomicAdd(&g_cursor[dst], 1);
    g_csr_src[pos] = src;
}

__global__ void k_dinv() {
    int i = blockIdx.x * blockDim.x + threadIdx.x;
    if (i < Nn) g_dinv[i] = rsqrtf((float)(g_deg[i] + 1));  // +1 self loop
}

// ---------------------------------------------------------------------------
// Tiled fp32 GEMM:  C[M,Ncols] = A[M,K] @ B[K,Ncols]
// ---------------------------------------------------------------------------
template <int BM, int BN, int BK, int TM, int TN>
__global__ void __launch_bounds__(256)
sgemm_kernel(const float* __restrict__ A, const float* __restrict__ B,
             float* __restrict__ C, int M, int Ncols, int K) {
    constexpr int NT = (BM / TM) * (BN / TN);  // 256
    __shared__ float As[BK][BM + 4];
    __shared__ float Bs[BK][BN];
    const int tid  = threadIdx.x;
    const int row0 = blockIdx.x * BM;
    const int col0 = blockIdx.y * BN;
    const int tcn  = tid % (BN / TN);
    const int trm  = tid / (BN / TN);

    float acc[TM][TN];
#pragma unroll
    for (int i = 0; i < TM; i++)
#pragma unroll
        for (int j = 0; j < TN; j++) acc[i][j] = 0.f;

    for (int k0 = 0; k0 < K; k0 += BK) {
#pragma unroll
        for (int i = tid; i < BM * (BK / 4); i += NT) {
            int r  = i / (BK / 4);
            int kq = (i % (BK / 4)) * 4;
            int grow = row0 + r;
            float4 v = make_float4(0.f, 0.f, 0.f, 0.f);
            if (grow < M)
                v = *reinterpret_cast<const float4*>(&A[(size_t)grow * K + k0 + kq]);
            As[kq + 0][r] = v.x; As[kq + 1][r] = v.y;
            As[kq + 2][r] = v.z; As[kq + 3][r] = v.w;
        }
#pragma unroll
        for (int i = tid; i < BK * (BN / 4); i += NT) {
            int kk = i / (BN / 4);
            int cq = (i % (BN / 4)) * 4;
            *reinterpret_cast<float4*>(&Bs[kk][cq]) =
                *reinterpret_cast<const float4*>(&B[(size_t)(k0 + kk) * Ncols + col0 + cq]);
        }
        __syncthreads();
#pragma unroll
        for (int kk = 0; kk < BK; kk++) {
            float a[TM], b[TN];
#pragma unroll
            for (int i = 0; i < TM; i += 4) {
                float4 av = *reinterpret_cast<const float4*>(&As[kk][trm * TM + i]);
                a[i] = av.x; a[i + 1] = av.y; a[i + 2] = av.z; a[i + 3] = av.w;
            }
#pragma unroll
            for (int j = 0; j < TN; j += 4) {
                float4 bv = *reinterpret_cast<const float4*>(&Bs[kk][tcn * TN + j]);
                b[j] = bv.x; b[j + 1] = bv.y; b[j + 2] = bv.z; b[j + 3] = bv.w;
            }
#pragma unroll
            for (int i = 0; i < TM; i++)
#pragma unroll
                for (int j = 0; j < TN; j++)
                    acc[i][j] = fmaf(a[i], b[j], acc[i][j]);
        }
        __syncthreads();
    }
#pragma unroll
    for (int i = 0; i < TM; i++) {
        int grow = row0 + trm * TM + i;
        if (grow >= M) continue;
#pragma unroll
        for (int j = 0; j < TN; j += 4) {
            float4 v = make_float4(acc[i][j], acc[i][j + 1], acc[i][j + 2], acc[i][j + 3]);
            *reinterpret_cast<float4*>(&C[(size_t)grow * Ncols + col0 + tcn * TN + j]) = v;
        }
    }
}

// ---------------------------------------------------------------------------
// GCN aggregation, layer 1 (128 feats): warp per node, lane = one float4.
// out = segment_sum(norm * Hlin[src]) + self + bias, then relu.
// ---------------------------------------------------------------------------
__global__ void k_agg128(const float* __restrict__ bias) {
    int node = blockIdx.x * (blockDim.x >> 5) + (threadIdx.x >> 5);
    int lane = threadIdx.x & 31;
    if (node >= Nn) return;
    const float di = g_dinv[node];
    const float4* H4 = reinterpret_cast<const float4*>(g_Hlin);

    float4 v = H4[(size_t)node * 32 + lane];
    const float sc = di * di;
    float4 acc = make_float4(v.x * sc, v.y * sc, v.z * sc, v.w * sc);

    int s = g_rowstart[node], e = g_rowstart[node + 1];
    int i = s;
    int src_next = (i < e) ? g_csr_src[i] : 0;
    for (; i < e;) {
        int src = src_next;
        ++i;
        if (i < e) src_next = g_csr_src[i];
        float c = g_dinv[src] * di;
        float4 u = H4[(size_t)src * 32 + lane];
        acc.x = fmaf(c, u.x, acc.x);
        acc.y = fmaf(c, u.y, acc.y);
        acc.z = fmaf(c, u.z, acc.z);
        acc.w = fmaf(c, u.w, acc.w);
    }
    float4 b = reinterpret_cast<const float4*>(bias)[lane];
    acc.x = fmaxf(acc.x + b.x, 0.f);
    acc.y = fmaxf(acc.y + b.y, 0.f);
    acc.z = fmaxf(acc.z + b.z, 0.f);
    acc.w = fmaxf(acc.w + b.w, 0.f);
    reinterpret_cast<float4*>(g_Hagg)[(size_t)node * 32 + lane] = acc;
}

// Layer 2 (64 feats): warp per node, lane = one float2. No relu.
__global__ void k_agg64(const float* __restrict__ bias) {
    int node = blockIdx.x * (blockDim.x >> 5) + (threadIdx.x >> 5);
    int lane = threadIdx.x & 31;
    if (node >= Nn) return;
    const float di = g_dinv[node];
    const float2* H2 = reinterpret_cast<const float2*>(g_H2lin);

    float2 v = H2[(size_t)node * 32 + lane];
    const float sc = di * di;
    float2 acc = make_float2(v.x * sc, v.y * sc);

    int s = g_rowstart[node], e = g_rowstart[node + 1];
    int i = s;
    int src_next = (i < e) ? g_csr_src[i] : 0;
    for (; i < e;) {
        int src = src_next;
        ++i;
        if (i < e) src_next = g_csr_src[i];
        float c = g_dinv[src] * di;
        float2 u = H2[(size_t)src * 32 + lane];
        acc.x = fmaf(c, u.x, acc.x);
        acc.y = fmaf(c, u.y, acc.y);
    }
    float2 b = reinterpret_cast<const float2*>(bias)[lane];
    acc.x += b.x;
    acc.y += b.y;
    reinterpret_cast<float2*>(g_Z)[(size_t)node * 32 + lane] = acc;
}

// ---------------------------------------------------------------------------
// Scores: 16 threads per edge; out[0:EP] = pos, out[EP:2EP] = neg.
// ---------------------------------------------------------------------------
__global__ void k_score(const void* __restrict__ pos_e, const void* __restrict__ neg_e,
                        float* __restrict__ out) {
    int gt = blockIdx.x * blockDim.x + threadIdx.x;
    int g  = gt >> 4;
    int l  = gt & 15;
    if (g >= 2 * EPp) return;
    const int is64 = g_is64;
    int a, b;
    if (g < EPp) {
        a = ld_idx(pos_e, g, is64);
        b = ld_idx(pos_e, EPp + g, is64);
    } else {
        int gg = g - EPp;
        a = ld_idx(neg_e, gg, is64);
        b = ld_idx(neg_e, EPp + gg, is64);
    }
    const float4* Z4 = reinterpret_cast<const float4*>(g_Z);
    float4 za = Z4[(size_t)a * 16 + l];
    float4 zb = Z4[(size_t)b * 16 + l];
    float p = za.x * zb.x + za.y * zb.y + za.z * zb.z + za.w * zb.w;
#pragma unroll
    for (int off = 8; off > 0; off >>= 1)
        p += __shfl_down_sync(0xffffffffu, p, off, 16);
    if (l == 0) out[g] = p;
}

// ---------------------------------------------------------------------------
// Launch
// ---------------------------------------------------------------------------
extern "C" void kernel_launch(void* const* d_in, const int* in_sizes, int n_in,
                              void* d_out, int out_size) {
    const float* x    = (const float*)d_in[0];
    const void*  edge = d_in[1];
    const void*  pose = d_in[2];
    const void*  nege = d_in[3];
    const float* W1   = (const float*)d_in[4];
    const float* b1   = (const float*)d_in[5];
    const float* W2   = (const float*)d_in[6];
    const float* b2   = (const float*)d_in[7];
    float* out = (float*)d_out;

    float* Hlin;  cudaGetSymbolAddress((void**)&Hlin,  g_Hlin);
    float* Hagg;  cudaGetSymbolAddress((void**)&Hagg,  g_Hagg);
    float* H2lin; cudaGetSymbolAddress((void**)&H2lin, g_H2lin);

    // CSR build (reused by both layers)
    k_detect<<<1, 256>>>((const int*)edge);
    k_zero_deg<<<(Nn + 255) / 256, 256>>>();
    k_count<<<(Ee + 255) / 256, 256>>>(edge);
    k_scan<<<1, 1024>>>();
    k_fill<<<(Ee + 255) / 256, 256>>>(edge);
    k_dinv<<<(Nn + 255) / 256, 256>>>();

    // Layer 1: Hlin = x @ W1 ; Hagg = relu(agg(Hlin) + b1)
    sgemm_kernel<64, 128, 16, 8, 4><<<dim3((Nn + 63) / 64, 1), 256>>>(
        x, W1, Hlin, Nn, HIDC, INCH);
    k_agg128<<<(Nn + 7) / 8, 256>>>(b1);

    // Layer 2: H2lin = Hagg @ W2 ; Z = agg(H2lin) + b2
    sgemm_kernel<64, 64, 16, 4, 4><<<dim3((Nn + 63) / 64, 1), 256>>>(
        Hagg, W2, H2lin, Nn, OUTC, HIDC);
    k_agg64<<<(Nn + 7) / 8, 256>>>(b2);

    // Scores
    k_score<<<(2 * EPp * 16 + 255) / 256, 256>>>(pose, nege, out);
}

// round 3
// speedup vs baseline: 1.4108x; 1.4108x over previous
#include <cuda_runtime.h>
#include <cuda_bf16.h>
#include <stdint.h>

// Problem constants
#define Nn    100000
#define INCH  256
#define HIDC  128
#define OUTC  64
#define Ee    1600000
#define EPp   500000

// ---------------------------------------------------------------------------
// Scratch (no allocations allowed -> __device__ globals)
// ---------------------------------------------------------------------------
__device__ float g_Hlin[(size_t)Nn * HIDC];   // x @ W1
__device__ float g_Hagg[(size_t)Nn * HIDC];   // relu(gcn1)
__device__ float g_H2lin[(size_t)Nn * OUTC];  // Hagg @ W2
__device__ float g_Z[(size_t)Nn * OUTC];      // gcn2 output
__device__ float g_dinv[Nn];
__device__ int   g_deg[Nn];
__device__ int   g_rowstart[Nn];
__device__ int   g_cursor[Nn];
__device__ int   g_csr_src[Ee];
__device__ int   g_is64;
__device__ int   g_alloc_ctr;

// ---------------------------------------------------------------------------
// Index helper: edge tensors may be int32 or int64 depending on jax x64 mode.
// ---------------------------------------------------------------------------
__device__ __forceinline__ int ld_idx(const void* p, int i, int is64) {
    if (is64) return (int)((const long long*)p)[i];
    return ((const int*)p)[i];
}

// Detect int64 vs int32: for int64 little-endian values < 2^31 every odd
// 32-bit word is zero. For int32 random indices in [0,100000) this is
// impossible over 2048 samples. Deterministic for fixed inputs.
__global__ void k_detect(const int* __restrict__ p) {
    __shared__ int any;
    if (threadIdx.x == 0) any = 0;
    __syncthreads();
    for (int i = threadIdx.x; i < 2048; i += blockDim.x)
        if (p[2 * i + 1] != 0) any = 1;
    __syncthreads();
    if (threadIdx.x == 0) g_is64 = any ? 0 : 1;
}

__global__ void k_zero_deg() {
    int i = blockIdx.x * blockDim.x + threadIdx.x;
    if (i < Nn) g_deg[i] = 0;
    if (i == 0) g_alloc_ctr = 0;
}

__global__ void k_count(const void* __restrict__ edge) {
    int e = blockIdx.x * blockDim.x + threadIdx.x;
    if (e >= Ee) return;
    const int is64 = g_is64;
    int dst = ld_idx(edge, Ee + e, is64);
    atomicAdd(&g_deg[dst], 1);
}

// ---------------------------------------------------------------------------
// Parallel segment allocation (replaces the 161us single-block serial scan).
// Slice ORDER across nodes is arbitrary (one atomicAdd per block); each node
// still owns a contiguous [rowstart, rowstart+deg) slice, which is all the
// aggregation needs.
// ---------------------------------------------------------------------------
__global__ void k_alloc() {
    __shared__ int warp_sums[8];
    __shared__ int s_base;
    int i = blockIdx.x * 256 + threadIdx.x;
    int lane = threadIdx.x & 31;
    int wid  = threadIdx.x >> 5;
    int d = (i < Nn) ? g_deg[i] : 0;

    // warp inclusive scan
    int s = d;
#pragma unroll
    for (int off = 1; off < 32; off <<= 1) {
        int v = __shfl_up_sync(0xffffffffu, s, off);
        if (lane >= off) s += v;
    }
    if (lane == 31) warp_sums[wid] = s;
    __syncthreads();

    if (wid == 0) {
        int ws = (lane < 8) ? warp_sums[lane] : 0;
#pragma unroll
        for (int off = 1; off < 8; off <<= 1) {
            int v = __shfl_up_sync(0xffffffffu, ws, off);
            if (lane >= off) ws += v;
        }
        if (lane == 7) s_base = atomicAdd(&g_alloc_ctr, ws);
        if (lane < 8) warp_sums[lane] = ws;  // inclusive warp prefixes
    }
    __syncthreads();

    if (i < Nn) {
        int base = s_base + (wid ? warp_sums[wid - 1] : 0);
        int start = base + s - d;
        g_rowstart[i] = start;
        g_cursor[i]   = start;
    }
}

__global__ void k_fill(const void* __restrict__ edge) {
    int e = blockIdx.x * blockDim.x + threadIdx.x;
    if (e >= Ee) return;
    const int is64 = g_is64;
    int src = ld_idx(edge, e, is64);
    int dst = ld_idx(edge, Ee + e, is64);
    int pos = atomicAdd(&g_cursor[dst], 1);
    g_csr_src[pos] = src;
}

__global__ void k_dinv() {
    int i = blockIdx.x * blockDim.x + threadIdx.x;
    if (i < Nn) g_dinv[i] = rsqrtf((float)(g_deg[i] + 1));  // +1 self loop
}

// ---------------------------------------------------------------------------
// Tiled fp32 GEMM:  C[M,Ncols] = A[M,K] @ B[K,Ncols]
// ---------------------------------------------------------------------------
template <int BM, int BN, int BK, int TM, int TN>
__global__ void __launch_bounds__(256)
sgemm_kernel(const float* __restrict__ A, const float* __restrict__ B,
             float* __restrict__ C, int M, int Ncols, int K) {
    constexpr int NT = (BM / TM) * (BN / TN);  // 256
    __shared__ float As[BK][BM + 4];
    __shared__ float Bs[BK][BN];
    const int tid  = threadIdx.x;
    const int row0 = blockIdx.x * BM;
    const int col0 = blockIdx.y * BN;
    const int tcn  = tid % (BN / TN);
    const int trm  = tid / (BN / TN);

    float acc[TM][TN];
#pragma unroll
    for (int i = 0; i < TM; i++)
#pragma unroll
        for (int j = 0; j < TN; j++) acc[i][j] = 0.f;

    for (int k0 = 0; k0 < K; k0 += BK) {
#pragma unroll
        for (int i = tid; i < BM * (BK / 4); i += NT) {
            int r  = i / (BK / 4);
            int kq = (i % (BK / 4)) * 4;
            int grow = row0 + r;
            float4 v = make_float4(0.f, 0.f, 0.f, 0.f);
            if (grow < M)
                v = *reinterpret_cast<const float4*>(&A[(size_t)grow * K + k0 + kq]);
            As[kq + 0][r] = v.x; As[kq + 1][r] = v.y;
            As[kq + 2][r] = v.z; As[kq + 3][r] = v.w;
        }
#pragma unroll
        for (int i = tid; i < BK * (BN / 4); i += NT) {
            int kk = i / (BN / 4);
            int cq = (i % (BN / 4)) * 4;
            *reinterpret_cast<float4*>(&Bs[kk][cq]) =
                *reinterpret_cast<const float4*>(&B[(size_t)(k0 + kk) * Ncols + col0 + cq]);
        }
        __syncthreads();
#pragma unroll
        for (int kk = 0; kk < BK; kk++) {
            float a[TM], b[TN];
#pragma unroll
            for (int i = 0; i < TM; i += 4) {
                float4 av = *reinterpret_cast<const float4*>(&As[kk][trm * TM + i]);
                a[i] = av.x; a[i + 1] = av.y; a[i + 2] = av.z; a[i + 3] = av.w;
            }
#pragma unroll
            for (int j = 0; j < TN; j += 4) {
                float4 bv = *reinterpret_cast<const float4*>(&Bs[kk][tcn * TN + j]);
                b[j] = bv.x; b[j + 1] = bv.y; b[j + 2] = bv.z; b[j + 3] = bv.w;
            }
#pragma unroll
            for (int i = 0; i < TM; i++)
#pragma unroll
                for (int j = 0; j < TN; j++)
                    acc[i][j] = fmaf(a[i], b[j], acc[i][j]);
        }
        __syncthreads();
    }
#pragma unroll
    for (int i = 0; i < TM; i++) {
        int grow = row0 + trm * TM + i;
        if (grow >= M) continue;
#pragma unroll
        for (int j = 0; j < TN; j += 4) {
            float4 v = make_float4(acc[i][j], acc[i][j + 1], acc[i][j + 2], acc[i][j + 3]);
            *reinterpret_cast<float4*>(&C[(size_t)grow * Ncols + col0 + tcn * TN + j]) = v;
        }
    }
}

// ---------------------------------------------------------------------------
// GCN aggregation, layer 1 (128 feats): warp per node, lane = one float4.
// out = segment_sum(norm * Hlin[src]) + self + bias, then relu.
// 2-deep index prefetch keeps the L2 gather pipeline fed.
// ---------------------------------------------------------------------------
__global__ void k_agg128(const float* __restrict__ bias) {
    int node = blockIdx.x * (blockDim.x >> 5) + (threadIdx.x >> 5);
    int lane = threadIdx.x & 31;
    if (node >= Nn) return;
    const float di = g_dinv[node];
    const float4* H4 = reinterpret_cast<const float4*>(g_Hlin);

    float4 v = H4[(size_t)node * 32 + lane];
    const float sc = di * di;
    float4 acc = make_float4(v.x * sc, v.y * sc, v.z * sc, v.w * sc);

    int s = g_rowstart[node];
    int e = s + g_deg[node];
    int i = s;
    int src0 = (i     < e) ? __ldg(&g_csr_src[i])     : 0;
    int src1 = (i + 1 < e) ? __ldg(&g_csr_src[i + 1]) : 0;
    for (; i < e; i++) {
        int src = src0;
        src0 = src1;
        src1 = (i + 2 < e) ? __ldg(&g_csr_src[i + 2]) : 0;
        float c = __ldg(&g_dinv[src]) * di;
        float4 u = H4[(size_t)src * 32 + lane];
        acc.x = fmaf(c, u.x, acc.x);
        acc.y = fmaf(c, u.y, acc.y);
        acc.z = fmaf(c, u.z, acc.z);
        acc.w = fmaf(c, u.w, acc.w);
    }
    float4 b = reinterpret_cast<const float4*>(bias)[lane];
    acc.x = fmaxf(acc.x + b.x, 0.f);
    acc.y = fmaxf(acc.y + b.y, 0.f);
    acc.z = fmaxf(acc.z + b.z, 0.f);
    acc.w = fmaxf(acc.w + b.w, 0.f);
    reinterpret_cast<float4*>(g_Hagg)[(size_t)node * 32 + lane] = acc;
}

// Layer 2 (64 feats): warp per node, lane = one float2. No relu.
__global__ void k_agg64(const float* __restrict__ bias) {
    int node = blockIdx.x * (blockDim.x >> 5) + (threadIdx.x >> 5);
    int lane = threadIdx.x & 31;
    if (node >= Nn) return;
    const float di = g_dinv[node];
    const float2* H2 = reinterpret_cast<const float2*>(g_H2lin);

    float2 v = H2[(size_t)node * 32 + lane];
    const float sc = di * di;
    float2 acc = make_float2(v.x * sc, v.y * sc);

    int s = g_rowstart[node];
    int e = s + g_deg[node];
    int i = s;
    int src0 = (i     < e) ? __ldg(&g_csr_src[i])     : 0;
    int src1 = (i + 1 < e) ? __ldg(&g_csr_src[i + 1]) : 0;
    for (; i < e; i++) {
        int src = src0;
        src0 = src1;
        src1 = (i + 2 < e) ? __ldg(&g_csr_src[i + 2]) : 0;
        float c = __ldg(&g_dinv[src]) * di;
        float2 u = H2[(size_t)src * 32 + lane];
        acc.x = fmaf(c, u.x, acc.x);
        acc.y = fmaf(c, u.y, acc.y);
    }
    float2 b = reinterpret_cast<const float2*>(bias)[lane];
    acc.x += b.x;
    acc.y += b.y;
    reinterpret_cast<float2*>(g_Z)[(size_t)node * 32 + lane] = acc;
}

// ---------------------------------------------------------------------------
// Scores: 16 threads per edge; out[0:EP] = pos, out[EP:2EP] = neg.
// ---------------------------------------------------------------------------
__global__ void k_score(const void* __restrict__ pos_e, const void* __restrict__ neg_e,
                        float* __restrict__ out) {
    int gt = blockIdx.x * blockDim.x + threadIdx.x;
    int g  = gt >> 4;
    int l  = gt & 15;
    if (g >= 2 * EPp) return;
    const int is64 = g_is64;
    int a, b;
    if (g < EPp) {
        a = ld_idx(pos_e, g, is64);
        b = ld_idx(pos_e, EPp + g, is64);
    } else {
        int gg = g - EPp;
        a = ld_idx(neg_e, gg, is64);
        b = ld_idx(neg_e, EPp + gg, is64);
    }
    const float4* Z4 = reinterpret_cast<const float4*>(g_Z);
    float4 za = Z4[(size_t)a * 16 + l];
    float4 zb = Z4[(size_t)b * 16 + l];
    float p = za.x * zb.x + za.y * zb.y + za.z * zb.z + za.w * zb.w;
#pragma unroll
    for (int off = 8; off > 0; off >>= 1)
        p += __shfl_down_sync(0xffffffffu, p, off, 16);
    if (l == 0) out[g] = p;
}

// ---------------------------------------------------------------------------
// Launch
// ---------------------------------------------------------------------------
extern "C" void kernel_launch(void* const* d_in, const int* in_sizes, int n_in,
                              void* d_out, int out_size) {
    const float* x    = (const float*)d_in[0];
    const void*  edge = d_in[1];
    const void*  pose = d_in[2];
    const void*  nege = d_in[3];
    const float* W1   = (const float*)d_in[4];
    const float* b1   = (const float*)d_in[5];
    const float* W2   = (const float*)d_in[6];
    const float* b2   = (const float*)d_in[7];
    float* out = (float*)d_out;

    float* Hlin;  cudaGetSymbolAddress((void**)&Hlin,  g_Hlin);
    float* Hagg;  cudaGetSymbolAddress((void**)&Hagg,  g_Hagg);
    float* H2lin; cudaGetSymbolAddress((void**)&H2lin, g_H2lin);

    // CSR build (reused by both layers)
    k_detect<<<1, 256>>>((const int*)edge);
    k_zero_deg<<<(Nn + 255) / 256, 256>>>();
    k_count<<<(Ee + 255) / 256, 256>>>(edge);
    k_alloc<<<(Nn + 255) / 256, 256>>>();
    k_fill<<<(Ee + 255) / 256, 256>>>(edge);
    k_dinv<<<(Nn + 255) / 256, 256>>>();

    // Layer 1: Hlin = x @ W1 ; Hagg = relu(agg(Hlin) + b1)
    sgemm_kernel<64, 128, 16, 8, 4><<<dim3((Nn + 63) / 64, 1), 256>>>(
        x, W1, Hlin, Nn, HIDC, INCH);
    k_agg128<<<(Nn + 7) / 8, 256>>>(b1);

    // Layer 2: H2lin = Hagg @ W2 ; Z = agg(H2lin) + b2
    sgemm_kernel<64, 64, 16, 4, 4><<<dim3((Nn + 63) / 64, 1), 256>>>(
        Hagg, W2, H2lin, Nn, OUTC, HIDC);
    k_agg64<<<(Nn + 7) / 8, 256>>>(b2);

    // Scores
    k_score<<<(2 * EPp * 16 + 255) / 256, 256>>>(pose, nege, out);
}

// round 5
// speedup vs baseline: 1.7563x; 1.2449x over previous
#include <cuda_runtime.h>
#include <cuda_bf16.h>
#include <stdint.h>

// Problem constants
#define Nn    100000
#define INCH  256
#define HIDC  128
#define OUTC  64
#define Ee    1600000
#define EPp   500000

// ---------------------------------------------------------------------------
// Scratch (no allocations allowed -> __device__ globals)
// ---------------------------------------------------------------------------
__device__ float g_Hlin[(size_t)Nn * HIDC];   // x @ W1
__device__ float g_Hagg[(size_t)Nn * HIDC];   // relu(gcn1)
__device__ float g_H2lin[(size_t)Nn * OUTC];  // Hagg @ W2
__device__ float g_Z[(size_t)Nn * OUTC];      // gcn2 output
__device__ float g_dinv[Nn];
__device__ int   g_deg[Nn];
__device__ int   g_rowstart[Nn];
__device__ int   g_cursor[Nn];
__device__ int   g_csr_src[Ee];
__device__ int   g_is64;
__device__ int   g_alloc_ctr;

// ---------------------------------------------------------------------------
// Index helper: edge tensors may be int32 or int64 depending on jax x64 mode.
// ---------------------------------------------------------------------------
__device__ __forceinline__ int ld_idx(const void* p, int i, int is64) {
    if (is64) return (int)((const long long*)p)[i];
    return ((const int*)p)[i];
}

__global__ void k_detect(const int* __restrict__ p) {
    __shared__ int any;
    if (threadIdx.x == 0) any = 0;
    __syncthreads();
    for (int i = threadIdx.x; i < 2048; i += blockDim.x)
        if (p[2 * i + 1] != 0) any = 1;
    __syncthreads();
    if (threadIdx.x == 0) g_is64 = any ? 0 : 1;
}

__global__ void k_zero_deg() {
    int i = blockIdx.x * blockDim.x + threadIdx.x;
    if (i < Nn) g_deg[i] = 0;
    if (i == 0) g_alloc_ctr = 0;
}

__global__ void k_count(const void* __restrict__ edge) {
    int e = blockIdx.x * blockDim.x + threadIdx.x;
    if (e >= Ee) return;
    const int is64 = g_is64;
    int dst = ld_idx(edge, Ee + e, is64);
    atomicAdd(&g_deg[dst], 1);
}

// Parallel segment allocation; slice order across nodes is arbitrary.
__global__ void k_alloc() {
    __shared__ int warp_sums[8];
    __shared__ int s_base;
    int i = blockIdx.x * 256 + threadIdx.x;
    int lane = threadIdx.x & 31;
    int wid  = threadIdx.x >> 5;
    int d = (i < Nn) ? g_deg[i] : 0;

    int s = d;
#pragma unroll
    for (int off = 1; off < 32; off <<= 1) {
        int v = __shfl_up_sync(0xffffffffu, s, off);
        if (lane >= off) s += v;
    }
    if (lane == 31) warp_sums[wid] = s;
    __syncthreads();

    if (wid == 0) {
        int ws = (lane < 8) ? warp_sums[lane] : 0;
#pragma unroll
        for (int off = 1; off < 8; off <<= 1) {
            int v = __shfl_up_sync(0xffffffffu, ws, off);
            if (lane >= off) ws += v;
        }
        if (lane == 7) s_base = atomicAdd(&g_alloc_ctr, ws);
        if (lane < 8) warp_sums[lane] = ws;
    }
    __syncthreads();

    if (i < Nn) {
        int base = s_base + (wid ? warp_sums[wid - 1] : 0);
        int start = base + s - d;
        g_rowstart[i] = start;
        g_cursor[i]   = start;
    }
}

__global__ void k_fill(const void* __restrict__ edge) {
    int e = blockIdx.x * blockDim.x + threadIdx.x;
    if (e >= Ee) return;
    const int is64 = g_is64;
    int src = ld_idx(edge, e, is64);
    int dst = ld_idx(edge, Ee + e, is64);
    int pos = atomicAdd(&g_cursor[dst], 1);
    g_csr_src[pos] = src;
}

__global__ void k_dinv() {
    int i = blockIdx.x * blockDim.x + threadIdx.x;
    if (i < Nn) g_dinv[i] = rsqrtf((float)(g_deg[i] + 1));  // +1 self loop
}

// ---------------------------------------------------------------------------
// TF32 tensor-core GEMM for layer 1:  C[M,128] = A[M,256] @ B[256,128]
// CTA tile 128x128x32, 8 warps (4x2), warp tile 32x64, mma m16n8k8.
// ---------------------------------------------------------------------------
__device__ __forceinline__ uint32_t f2tf32(float f) {
    uint32_t u;
    asm("cvt.rna.tf32.f32 %0, %1;" : "=r"(u) : "f"(f));
    return u;
}

#define AS_STRIDE 36   // conflict-free for fragment loads (pad 4)
#define BS_STRIDE 136  // conflict-free for fragment loads (pad 8)

__global__ void __launch_bounds__(256)
gemm1_tf32(const float* __restrict__ A, const float* __restrict__ B,
           float* __restrict__ C) {
    __shared__ uint32_t As[128 * AS_STRIDE];
    __shared__ uint32_t Bs[32 * BS_STRIDE];
    const int tid  = threadIdx.x;
    const int lane = tid & 31;
    const int warp = tid >> 5;
    const int wm = warp >> 1;          // 0..3
    const int wn = warp & 1;           // 0..1
    const int row0 = blockIdx.x * 128;
    const int qr = lane >> 2;          // 0..7
    const int qc = lane & 3;           // 0..3

    float c[2][8][4];
#pragma unroll
    for (int mt = 0; mt < 2; mt++)
#pragma unroll
        for (int nt = 0; nt < 8; nt++)
#pragma unroll
            for (int k = 0; k < 4; k++) c[mt][nt][k] = 0.f;

    for (int k0 = 0; k0 < INCH; k0 += 32) {
        // Stage A tile (128 x 32): each thread 4 x float4, convert to tf32.
#pragma unroll
        for (int t = 0; t < 4; t++) {
            int r  = (tid >> 3) + t * 32;
            int kq = (tid & 7) * 4;
            int grow = row0 + r;
            float4 v = make_float4(0.f, 0.f, 0.f, 0.f);
            if (grow < Nn)
                v = *reinterpret_cast<const float4*>(&A[(size_t)grow * INCH + k0 + kq]);
            uint4 u = make_uint4(f2tf32(v.x), f2tf32(v.y), f2tf32(v.z), f2tf32(v.w));
            *reinterpret_cast<uint4*>(&As[r * AS_STRIDE + kq]) = u;
        }
        // Stage B tile (32 x 128).
#pragma unroll
        for (int t = 0; t < 4; t++) {
            int kk = (tid >> 5) + t * 8;
            int cc = (tid & 31) * 4;
            float4 v = *reinterpret_cast<const float4*>(&B[(size_t)(k0 + kk) * HIDC + cc]);
            uint4 u = make_uint4(f2tf32(v.x), f2tf32(v.y), f2tf32(v.z), f2tf32(v.w));
            *reinterpret_cast<uint4*>(&Bs[kk * BS_STRIDE + cc]) = u;
        }
        __syncthreads();

#pragma unroll
        for (int ks = 0; ks < 4; ks++) {
            const int kb = ks * 8;
            uint32_t a[2][4], b[8][2];
#pragma unroll
            for (int mt = 0; mt < 2; mt++) {
                int r = wm * 32 + mt * 16 + qr;
                a[mt][0] = As[r * AS_STRIDE + kb + qc];
                a[mt][1] = As[(r + 8) * AS_STRIDE + kb + qc];
                a[mt][2] = As[r * AS_STRIDE + kb + qc + 4];
                a[mt][3] = As[(r + 8) * AS_STRIDE + kb + qc + 4];
            }
#pragma unroll
            for (int nt = 0; nt < 8; nt++) {
                int n = wn * 64 + nt * 8 + qr;
                b[nt][0] = Bs[(kb + qc) * BS_STRIDE + n];
                b[nt][1] = Bs[(kb + qc + 4) * BS_STRIDE + n];
            }
#pragma unroll
            for (int mt = 0; mt < 2; mt++)
#pragma unroll
                for (int nt = 0; nt < 8; nt++) {
                    asm volatile(
                        "mma.sync.aligned.m16n8k8.row.col.f32.tf32.tf32.f32 "
                        "{%0,%1,%2,%3}, {%4,%5,%6,%7}, {%8,%9}, {%0,%1,%2,%3};\n"
                        : "+f"(c[mt][nt][0]), "+f"(c[mt][nt][1]),
                          "+f"(c[mt][nt][2]), "+f"(c[mt][nt][3])
                        : "r"(a[mt][0]), "r"(a[mt][1]), "r"(a[mt][2]), "r"(a[mt][3]),
                          "r"(b[nt][0]), "r"(b[nt][1]));
                }
        }
        __syncthreads();
    }

    // Epilogue: c0/c1 at (row, 2*qc), c2/c3 at (row+8, 2*qc).
#pragma unroll
    for (int mt = 0; mt < 2; mt++) {
        int r = row0 + wm * 32 + mt * 16 + qr;
#pragma unroll
        for (int nt = 0; nt < 8; nt++) {
            int cb = wn * 64 + nt * 8 + qc * 2;
            if (r < Nn)
                *reinterpret_cast<float2*>(&C[(size_t)r * HIDC + cb]) =
                    make_float2(c[mt][nt][0], c[mt][nt][1]);
            if (r + 8 < Nn)
                *reinterpret_cast<float2*>(&C[(size_t)(r + 8) * HIDC + cb]) =
                    make_float2(c[mt][nt][2], c[mt][nt][3]);
        }
    }
}

// ---------------------------------------------------------------------------
// Tiled fp32 GEMM (kept for layer 2; precision + attribution hedge)
// ---------------------------------------------------------------------------
template <int BM, int BN, int BK, int TM, int TN>
__global__ void __launch_bounds__(256)
sgemm_kernel(const float* __restrict__ A, const float* __restrict__ B,
             float* __restrict__ C, int M, int Ncols, int K) {
    constexpr int NT = (BM / TM) * (BN / TN);  // 256
    __shared__ float As[BK][BM + 4];
    __shared__ float Bs[BK][BN];
    const int tid  = threadIdx.x;
    const int row0 = blockIdx.x * BM;
    const int col0 = blockIdx.y * BN;
    const int tcn  = tid % (BN / TN);
    const int trm  = tid / (BN / TN);

    float acc[TM][TN];
#pragma unroll
    for (int i = 0; i < TM; i++)
#pragma unroll
        for (int j = 0; j < TN; j++) acc[i][j] = 0.f;

    for (int k0 = 0; k0 < K; k0 += BK) {
#pragma unroll
        for (int i = tid; i < BM * (BK / 4); i += NT) {
            int r  = i / (BK / 4);
            int kq = (i % (BK / 4)) * 4;
            int grow = row0 + r;
            float4 v = make_float4(0.f, 0.f, 0.f, 0.f);
            if (grow < M)
                v = *reinterpret_cast<const float4*>(&A[(size_t)grow * K + k0 + kq]);
            As[kq + 0][r] = v.x; As[kq + 1][r] = v.y;
            As[kq + 2][r] = v.z; As[kq + 3][r] = v.w;
        }
#pragma unroll
        for (int i = tid; i < BK * (BN / 4); i += NT) {
            int kk = i / (BN / 4);
            int cq = (i % (BN / 4)) * 4;
            *reinterpret_cast<float4*>(&Bs[kk][cq]) =
                *reinterpret_cast<const float4*>(&B[(size_t)(k0 + kk) * Ncols + col0 + cq]);
        }
        __syncthreads();
#pragma unroll
        for (int kk = 0; kk < BK; kk++) {
            float a[TM], b[TN];
#pragma unroll
            for (int i = 0; i < TM; i += 4) {
                float4 av = *reinterpret_cast<const float4*>(&As[kk][trm * TM + i]);
                a[i] = av.x; a[i + 1] = av.y; a[i + 2] = av.z; a[i + 3] = av.w;
            }
#pragma unroll
            for (int j = 0; j < TN; j += 4) {
                float4 bv = *reinterpret_cast<const float4*>(&Bs[kk][tcn * TN + j]);
                b[j] = bv.x; b[j + 1] = bv.y; b[j + 2] = bv.z; b[j + 3] = bv.w;
            }
#pragma unroll
            for (int i = 0; i < TM; i++)
#pragma unroll
                for (int j = 0; j < TN; j++)
                    acc[i][j] = fmaf(a[i], b[j], acc[i][j]);
        }
        __syncthreads();
    }
#pragma unroll
    for (int i = 0; i < TM; i++) {
        int grow = row0 + trm * TM + i;
        if (grow >= M) continue;
#pragma unroll
        for (int j = 0; j < TN; j += 4) {
            float4 v = make_float4(acc[i][j], acc[i][j + 1], acc[i][j + 2], acc[i][j + 3]);
            *reinterpret_cast<float4*>(&C[(size_t)grow * Ncols + col0 + tcn * TN + j]) = v;
        }
    }
}

// ---------------------------------------------------------------------------
// GCN aggregation, layer 1 (128 feats): warp per node, lane = one float4.
// ---------------------------------------------------------------------------
__global__ void k_agg128(const float* __restrict__ bias) {
    int node = blockIdx.x * (blockDim.x >> 5) + (threadIdx.x >> 5);
    int lane = threadIdx.x & 31;
    if (node >= Nn) return;
    const float di = g_dinv[node];
    const float4* H4 = reinterpret_cast<const float4*>(g_Hlin);

    float4 v = H4[(size_t)node * 32 + lane];
    const float sc = di * di;
    float4 acc = make_float4(v.x * sc, v.y * sc, v.z * sc, v.w * sc);

    int s = g_rowstart[node];
    int e = s + g_deg[node];
    int i = s;
    int src0 = (i     < e) ? __ldg(&g_csr_src[i])     : 0;
    int src1 = (i + 1 < e) ? __ldg(&g_csr_src[i + 1]) : 0;
    for (; i < e; i++) {
        int src = src0;
        src0 = src1;
        src1 = (i + 2 < e) ? __ldg(&g_csr_src[i + 2]) : 0;
        float c = __ldg(&g_dinv[src]) * di;
        float4 u = H4[(size_t)src * 32 + lane];
        acc.x = fmaf(c, u.x, acc.x);
        acc.y = fmaf(c, u.y, acc.y);
        acc.z = fmaf(c, u.z, acc.z);
        acc.w = fmaf(c, u.w, acc.w);
    }
    float4 b = reinterpret_cast<const float4*>(bias)[lane];
    acc.x = fmaxf(acc.x + b.x, 0.f);
    acc.y = fmaxf(acc.y + b.y, 0.f);
    acc.z = fmaxf(acc.z + b.z, 0.f);
    acc.w = fmaxf(acc.w + b.w, 0.f);
    reinterpret_cast<float4*>(g_Hagg)[(size_t)node * 32 + lane] = acc;
}

// Layer 2 (64 feats): warp per node, lane = one float2. No relu.
__global__ void k_agg64(const float* __restrict__ bias) {
    int node = blockIdx.x * (blockDim.x >> 5) + (threadIdx.x >> 5);
    int lane = threadIdx.x & 31;
    if (node >= Nn) return;
    const float di = g_dinv[node];
    const float2* H2 = reinterpret_cast<const float2*>(g_H2lin);

    float2 v = H2[(size_t)node * 32 + lane];
    const float sc = di * di;
    float2 acc = make_float2(v.x * sc, v.y * sc);

    int s = g_rowstart[node];
    int e = s + g_deg[node];
    int i = s;
    int src0 = (i     < e) ? __ldg(&g_csr_src[i])     : 0;
    int src1 = (i + 1 < e) ? __ldg(&g_csr_src[i + 1]) : 0;
    for (; i < e; i++) {
        int src = src0;
        src0 = src1;
        src1 = (i + 2 < e) ? __ldg(&g_csr_src[i + 2]) : 0;
        float c = __ldg(&g_dinv[src]) * di;
        float2 u = H2[(size_t)src * 32 + lane];
        acc.x = fmaf(c, u.x, acc.x);
        acc.y = fmaf(c, u.y, acc.y);
    }
    float2 b = reinterpret_cast<const float2*>(bias)[lane];
    acc.x += b.x;
    acc.y += b.y;
    reinterpret_cast<float2*>(g_Z)[(size_t)node * 32 + lane] = acc;
}

// ---------------------------------------------------------------------------
// Scores: 16 threads per edge; out[0:EP] = pos, out[EP:2EP] = neg.
// ---------------------------------------------------------------------------
__global__ void k_score(const void* __restrict__ pos_e, const void* __restrict__ neg_e,
                        float* __restrict__ out) {
    int gt = blockIdx.x * blockDim.x + threadIdx.x;
    int g  = gt >> 4;
    int l  = gt & 15;
    if (g >= 2 * EPp) return;
    const int is64 = g_is64;
    int a, b;
    if (g < EPp) {
        a = ld_idx(pos_e, g, is64);
        b = ld_idx(pos_e, EPp + g, is64);
    } else {
        int gg = g - EPp;
        a = ld_idx(neg_e, gg, is64);
        b = ld_idx(neg_e, EPp + gg, is64);
    }
    const float4* Z4 = reinterpret_cast<const float4*>(g_Z);
    float4 za = Z4[(size_t)a * 16 + l];
    float4 zb = Z4[(size_t)b * 16 + l];
    float p = za.x * zb.x + za.y * zb.y + za.z * zb.z + za.w * zb.w;
#pragma unroll
    for (int off = 8; off > 0; off >>= 1)
        p += __shfl_down_sync(0xffffffffu, p, off, 16);
    if (l == 0) out[g] = p;
}

// ---------------------------------------------------------------------------
// Launch
// ---------------------------------------------------------------------------
extern "C" void kernel_launch(void* const* d_in, const int* in_sizes, int n_in,
                              void* d_out, int out_size) {
    const float* x    = (const float*)d_in[0];
    const void*  edge = d_in[1];
    const void*  pose = d_in[2];
    const void*  nege = d_in[3];
    const float* W1   = (const float*)d_in[4];
    const float* b1   = (const float*)d_in[5];
    const float* W2   = (const float*)d_in[6];
    const float* b2   = (const float*)d_in[7];
    float* out = (float*)d_out;

    float* Hlin;  cudaGetSymbolAddress((void**)&Hlin,  g_Hlin);
    float* Hagg;  cudaGetSymbolAddress((void**)&Hagg,  g_Hagg);
    float* H2lin; cudaGetSymbolAddress((void**)&H2lin, g_H2lin);

    // CSR build (reused by both layers)
    k_detect<<<1, 256>>>((const int*)edge);
    k_zero_deg<<<(Nn + 255) / 256, 256>>>();
    k_count<<<(Ee + 255) / 256, 256>>>(edge);
    k_alloc<<<(Nn + 255) / 256, 256>>>();
    k_fill<<<(Ee + 255) / 256, 256>>>(edge);
    k_dinv<<<(Nn + 255) / 256, 256>>>();

    // Layer 1: Hlin = x @ W1 (tf32 tensor cores); Hagg = relu(agg(Hlin) + b1)
    gemm1_tf32<<<(Nn + 127) / 128, 256>>>(x, W1, Hlin);
    k_agg128<<<(Nn + 7) / 8, 256>>>(b1);

    // Layer 2: H2lin = Hagg @ W2 (fp32) ; Z = agg(H2lin) + b2
    sgemm_kernel<64, 64, 16, 4, 4><<<dim3((Nn + 63) / 64, 1), 256>>>(
        Hagg, W2, H2lin, Nn, OUTC, HIDC);
    k_agg64<<<(Nn + 7) / 8, 256>>>(b2);

    // Scores
    k_score<<<(2 * EPp * 16 + 255) / 256, 256>>>(pose, nege, out);
}

// round 8
// speedup vs baseline: 1.9620x; 1.1171x over previous
#include <cuda_runtime.h>
#include <cuda_bf16.h>
#include <stdint.h>

// Problem constants
#define Nn    100000
#define INCH  256
#define HIDC  128
#define OUTC  64
#define Ee    1600000
#define EPp   500000

// ---------------------------------------------------------------------------
// Scratch (no allocations allowed -> __device__ globals)
// ---------------------------------------------------------------------------
__device__ __nv_bfloat16 g_Hlin[(size_t)Nn * HIDC];   // x @ W1 (bf16, gather source)
__device__ float         g_Hagg[(size_t)Nn * HIDC];   // relu(gcn1)  (fp32, GEMM2 input)
__device__ __nv_bfloat16 g_H2lin[(size_t)Nn * OUTC];  // Hagg @ W2 (bf16, gather source)
__device__ float         g_Z[(size_t)Nn * OUTC];      // gcn2 output (fp32, score source)
__device__ float g_dinv[Nn];
__device__ int   g_deg[Nn];
__device__ int   g_rowstart[Nn];
__device__ int   g_cursor[Nn];
__device__ int   g_csr_src[Ee];
__device__ int   g_is64;
__device__ int   g_alloc_ctr;

// ---------------------------------------------------------------------------
// Index helper: edge tensors may be int32 or int64 depending on jax x64 mode.
// ---------------------------------------------------------------------------
__device__ __forceinline__ int ld_idx(const void* p, int i, int is64) {
    if (is64) return (int)((const long long*)p)[i];
    return ((const int*)p)[i];
}

__global__ void k_detect(const int* __restrict__ p) {
    __shared__ int any;
    if (threadIdx.x == 0) any = 0;
    __syncthreads();
    for (int i = threadIdx.x; i < 2048; i += blockDim.x)
        if (p[2 * i + 1] != 0) any = 1;
    __syncthreads();
    if (threadIdx.x == 0) g_is64 = any ? 0 : 1;
}

__global__ void k_zero_deg() {
    int i = blockIdx.x * blockDim.x + threadIdx.x;
    if (i < Nn) g_deg[i] = 0;
    if (i == 0) g_alloc_ctr = 0;
}

__global__ void k_count(const void* __restrict__ edge) {
    int e = blockIdx.x * blockDim.x + threadIdx.x;
    if (e >= Ee) return;
    const int is64 = g_is64;
    int dst = ld_idx(edge, Ee + e, is64);
    atomicAdd(&g_deg[dst], 1);
}

// Parallel segment allocation; slice order across nodes is arbitrary.
// dinv computation fused in (deg already in registers).
__global__ void k_alloc() {
    __shared__ int warp_sums[8];
    __shared__ int s_base;
    int i = blockIdx.x * 256 + threadIdx.x;
    int lane = threadIdx.x & 31;
    int wid  = threadIdx.x >> 5;
    int d = (i < Nn) ? g_deg[i] : 0;

    int s = d;
#pragma unroll
    for (int off = 1; off < 32; off <<= 1) {
        int v = __shfl_up_sync(0xffffffffu, s, off);
        if (lane >= off) s += v;
    }
    if (lane == 31) warp_sums[wid] = s;
    __syncthreads();

    if (wid == 0) {
        int ws = (lane < 8) ? warp_sums[lane] : 0;
#pragma unroll
        for (int off = 1; off < 8; off <<= 1) {
            int v = __shfl_up_sync(0xffffffffu, ws, off);
            if (lane >= off) ws += v;
        }
        if (lane == 7) s_base = atomicAdd(&g_alloc_ctr, ws);
        if (lane < 8) warp_sums[lane] = ws;
    }
    __syncthreads();

    if (i < Nn) {
        int base = s_base + (wid ? warp_sums[wid - 1] : 0);
        int start = base + s - d;
        g_rowstart[i] = start;
        g_cursor[i]   = start;
        g_dinv[i]     = rsqrtf((float)(d + 1));  // +1 self loop
    }
}

__global__ void k_fill(const void* __restrict__ edge) {
    int e = blockIdx.x * blockDim.x + threadIdx.x;
    if (e >= Ee) return;
    const int is64 = g_is64;
    int src = ld_idx(edge, e, is64);
    int dst = ld_idx(edge, Ee + e, is64);
    int pos = atomicAdd(&g_cursor[dst], 1);
    g_csr_src[pos] = src;
}

// ---------------------------------------------------------------------------
// TF32 tensor-core GEMM:  C[M,NDIM] = A[M,KDIM] @ B[KDIM,NDIM], bf16 output.
// CTA tile 128 x NDIM x 32, 8 warps (4x2), warp tile 32 x NDIM/2, mma m16n8k8.
// ---------------------------------------------------------------------------
__device__ __forceinline__ uint32_t f2tf32(float f) {
    uint32_t u;
    asm("cvt.rna.tf32.f32 %0, %1;" : "=r"(u) : "f"(f));
    return u;
}

#define AS_STRIDE 36   // conflict-free for fragment loads (pad 4)

template <int KDIM, int NDIM>
__global__ void __launch_bounds__(256)
gemm_tf32(const float* __restrict__ A, const float* __restrict__ B,
          __nv_bfloat16* __restrict__ C) {
    constexpr int BSS   = NDIM + 8;       // B smem stride (pad 8 -> stride%32==8)
    constexpr int NFRAG = NDIM / 16;      // b fragments per warp (8 or 4)
    constexpr int NQ    = NDIM / 4;       // float4 cols in B tile
    constexpr int BITER = 32 * NQ / 256;  // B staging iterations (4 or 2)
    __shared__ uint32_t As[128 * AS_STRIDE];
    __shared__ uint32_t Bs[32 * BSS];
    const int tid  = threadIdx.x;
    const int lane = tid & 31;
    const int warp = tid >> 5;
    const int wm = warp >> 1;          // 0..3
    const int wn = warp & 1;           // 0..1
    const int row0 = blockIdx.x * 128;
    const int qr = lane >> 2;          // 0..7
    const int qc = lane & 3;           // 0..3

    float c[2][NFRAG][4];
#pragma unroll
    for (int mt = 0; mt < 2; mt++)
#pragma unroll
        for (int nt = 0; nt < NFRAG; nt++)
#pragma unroll
            for (int k = 0; k < 4; k++) c[mt][nt][k] = 0.f;

    for (int k0 = 0; k0 < KDIM; k0 += 32) {
        // Stage A tile (128 x 32): each thread 4 x float4, convert to tf32.
#pragma unroll
        for (int t = 0; t < 4; t++) {
            int r  = (tid >> 3) + t * 32;
            int kq = (tid & 7) * 4;
            int grow = row0 + r;
            float4 v = make_float4(0.f, 0.f, 0.f, 0.f);
            if (grow < Nn)
                v = *reinterpret_cast<const float4*>(&A[(size_t)grow * KDIM + k0 + kq]);
            uint4 u = make_uint4(f2tf32(v.x), f2tf32(v.y), f2tf32(v.z), f2tf32(v.w));
            *reinterpret_cast<uint4*>(&As[r * AS_STRIDE + kq]) = u;
        }
        // Stage B tile (32 x NDIM).
#pragma unroll
        for (int t = 0; t < BITER; t++) {
            int kk = tid / NQ + t * (256 / NQ);
            int cc = (tid % NQ) * 4;
            float4 v = *reinterpret_cast<const float4*>(&B[(size_t)(k0 + kk) * NDIM + cc]);
            uint4 u = make_uint4(f2tf32(v.x), f2tf32(v.y), f2tf32(v.z), f2tf32(v.w));
            *reinterpret_cast<uint4*>(&Bs[kk * BSS + cc]) = u;
        }
        __syncthreads();

#pragma unroll
        for (int ks = 0; ks < 4; ks++) {
            const int kb = ks * 8;
            uint32_t a[2][4], b[NFRAG][2];
#pragma unroll
            for (int mt = 0; mt < 2; mt++) {
                int r = wm * 32 + mt * 16 + qr;
                a[mt][0] = As[r * AS_STRIDE + kb + qc];
                a[mt][1] = As[(r + 8) * AS_STRIDE + kb + qc];
                a[mt][2] = As[r * AS_STRIDE + kb + qc + 4];
                a[mt][3] = As[(r + 8) * AS_STRIDE + kb + qc + 4];
            }
#pragma unroll
            for (int nt = 0; nt < NFRAG; nt++) {
                int n = wn * (NDIM / 2) + nt * 8 + qr;
                b[nt][0] = Bs[(kb + qc) * BSS + n];
                b[nt][1] = Bs[(kb + qc + 4) * BSS + n];
            }
#pragma unroll
            for (int mt = 0; mt < 2; mt++)
#pragma unroll
                for (int nt = 0; nt < NFRAG; nt++) {
                    asm volatile(
                        "mma.sync.aligned.m16n8k8.row.col.f32.tf32.tf32.f32 "
                        "{%0,%1,%2,%3}, {%4,%5,%6,%7}, {%8,%9}, {%0,%1,%2,%3};\n"
                        : "+f"(c[mt][nt][0]), "+f"(c[mt][nt][1]),
                          "+f"(c[mt][nt][2]), "+f"(c[mt][nt][3])
                        : "r"(a[mt][0]), "r"(a[mt][1]), "r"(a[mt][2]), "r"(a[mt][3]),
                          "r"(b[nt][0]), "r"(b[nt][1]));
                }
        }
        __syncthreads();
    }

    // Epilogue: bf16 pairs. c0/c1 -> (row, 2*qc), c2/c3 -> (row+8, 2*qc).
#pragma unroll
    for (int mt = 0; mt < 2; mt++) {
        int r = row0 + wm * 32 + mt * 16 + qr;
#pragma unroll
        for (int nt = 0; nt < NFRAG; nt++) {
            int cb = wn * (NDIM / 2) + nt * 8 + qc * 2;
            if (r < Nn)
                *reinterpret_cast<__nv_bfloat162*>(&C[(size_t)r * NDIM + cb]) =
                    __floats2bfloat162_rn(c[mt][nt][0], c[mt][nt][1]);
            if (r + 8 < Nn)
                *reinterpret_cast<__nv_bfloat162*>(&C[(size_t)(r + 8) * NDIM + cb]) =
                    __floats2bfloat162_rn(c[mt][nt][2], c[mt][nt][3]);
        }
    }
}

// ---------------------------------------------------------------------------
// GCN aggregation, layer 1 (128 feats, bf16 source): warp per node,
// lane = 4 feats (one uint2 = 4 bf16). Accumulate fp32, write Hagg fp32.
// ---------------------------------------------------------------------------
__global__ void k_agg128(const float* __restrict__ bias) {
    int node = blockIdx.x * (blockDim.x >> 5) + (threadIdx.x >> 5);
    int lane = threadIdx.x & 31;
    if (node >= Nn) return;
    const float di = g_dinv[node];
    const uint2* H = reinterpret_cast<const uint2*>(g_Hlin);  // 4 bf16 per elt

    uint2 sv = H[(size_t)node * 32 + lane];
    float2 s01 = __bfloat1622float2(*reinterpret_cast<__nv_bfloat162*>(&sv.x));
    float2 s23 = __bfloat1622float2(*reinterpret_cast<__nv_bfloat162*>(&sv.y));
    const float sc = di * di;
    float4 acc = make_float4(s01.x * sc, s01.y * sc, s23.x * sc, s23.y * sc);

    int s = g_rowstart[node];
    int e = s + g_deg[node];
    int i = s;
    int src0 = (i     < e) ? __ldg(&g_csr_src[i])     : 0;
    int src1 = (i + 1 < e) ? __ldg(&g_csr_src[i + 1]) : 0;
    for (; i < e; i++) {
        int src = src0;
        src0 = src1;
        src1 = (i + 2 < e) ? __ldg(&g_csr_src[i + 2]) : 0;
        float c = __ldg(&g_dinv[src]) * di;
        uint2 uv = H[(size_t)src * 32 + lane];
        float2 u01 = __bfloat1622float2(*reinterpret_cast<__nv_bfloat162*>(&uv.x));
        float2 u23 = __bfloat1622float2(*reinterpret_cast<__nv_bfloat162*>(&uv.y));
        acc.x = fmaf(c, u01.x, acc.x);
        acc.y = fmaf(c, u01.y, acc.y);
        acc.z = fmaf(c, u23.x, acc.z);
        acc.w = fmaf(c, u23.y, acc.w);
    }
    float4 b = reinterpret_cast<const float4*>(bias)[lane];
    acc.x = fmaxf(acc.x + b.x, 0.f);
    acc.y = fmaxf(acc.y + b.y, 0.f);
    acc.z = fmaxf(acc.z + b.z, 0.f);
    acc.w = fmaxf(acc.w + b.w, 0.f);
    reinterpret_cast<float4*>(g_Hagg)[(size_t)node * 32 + lane] = acc;
}

// Layer 2 (64 feats, bf16 source): warp per node, lane = 2 feats (one bf162).
// No relu; write Z fp32.
__global__ void k_agg64(const float* __restrict__ bias) {
    int node = blockIdx.x * (blockDim.x >> 5) + (threadIdx.x >> 5);
    int lane = threadIdx.x & 31;
    if (node >= Nn) return;
    const float di = g_dinv[node];
    const __nv_bfloat162* H = reinterpret_cast<const __nv_bfloat162*>(g_H2lin);

    float2 sv = __bfloat1622float2(H[(size_t)node * 32 + lane]);
    const float sc = di * di;
    float2 acc = make_float2(sv.x * sc, sv.y * sc);

    int s = g_rowstart[node];
    int e = s + g_deg[node];
    int i = s;
    int src0 = (i     < e) ? __ldg(&g_csr_src[i])     : 0;
    int src1 = (i + 1 < e) ? __ldg(&g_csr_src[i + 1]) : 0;
    for (; i < e; i++) {
        int src = src0;
        src0 = src1;
        src1 = (i + 2 < e) ? __ldg(&g_csr_src[i + 2]) : 0;
        float c = __ldg(&g_dinv[src]) * di;
        float2 u = __bfloat1622float2(H[(size_t)src * 32 + lane]);
        acc.x = fmaf(c, u.x, acc.x);
        acc.y = fmaf(c, u.y, acc.y);
    }
    float2 b = reinterpret_cast<const float2*>(bias)[lane];
    acc.x += b.x;
    acc.y += b.y;
    reinterpret_cast<float2*>(g_Z)[(size_t)node * 32 + lane] = acc;
}

// ---------------------------------------------------------------------------
// Scores: 16 threads per edge; out[0:EP] = pos, out[EP:2EP] = neg. fp32 Z.
// ---------------------------------------------------------------------------
__global__ void k_score(const void* __restrict__ pos_e, const void* __restrict__ neg_e,
                        float* __restrict__ out) {
    int gt = blockIdx.x * blockDim.x + threadIdx.x;
    int g  = gt >> 4;
    int l  = gt & 15;
    if (g >= 2 * EPp) return;
    const int is64 = g_is64;
    int a, b;
    if (g < EPp) {
        a = ld_idx(pos_e, g, is64);
        b = ld_idx(pos_e, EPp + g, is64);
    } else {
        int gg = g - EPp;
        a = ld_idx(neg_e, gg, is64);
        b = ld_idx(neg_e, EPp + gg, is64);
    }
    const float4* Z4 = reinterpret_cast<const float4*>(g_Z);
    float4 za = Z4[(size_t)a * 16 + l];
    float4 zb = Z4[(size_t)b * 16 + l];
    float p = za.x * zb.x + za.y * zb.y + za.z * zb.z + za.w * zb.w;
#pragma unroll
    for (int off = 8; off > 0; off >>= 1)
        p += __shfl_down_sync(0xffffffffu, p, off, 16);
    if (l == 0) out[g] = p;
}

// ---------------------------------------------------------------------------
// Launch
// ---------------------------------------------------------------------------
extern "C" void kernel_launch(void* const* d_in, const int* in_sizes, int n_in,
                              void* d_out, int out_size) {
    const float* x    = (const float*)d_in[0];
    const void*  edge = d_in[1];
    const void*  pose = d_in[2];
    const void*  nege = d_in[3];
    const float* W1   = (const float*)d_in[4];
    const float* b1   = (const float*)d_in[5];
    const float* W2   = (const float*)d_in[6];
    const float* b2   = (const float*)d_in[7];
    float* out = (float*)d_out;

    __nv_bfloat16* Hlin;  cudaGetSymbolAddress((void**)&Hlin,  g_Hlin);
    float*         Hagg;  cudaGetSymbolAddress((void**)&Hagg,  g_Hagg);
    __nv_bfloat16* H2lin; cudaGetSymbolAddress((void**)&H2lin, g_H2lin);

    // CSR build (reused by both layers)
    k_detect<<<1, 256>>>((const int*)edge);
    k_zero_deg<<<(Nn + 255) / 256, 256>>>();
    k_count<<<(Ee + 255) / 256, 256>>>(edge);
    k_alloc<<<(Nn + 255) / 256, 256>>>();   // also computes dinv
    k_fill<<<(Ee + 255) / 256, 256>>>(edge);

    // Layer 1: Hlin = x @ W1 (tf32 -> bf16); Hagg = relu(agg(Hlin) + b1) fp32
    gemm_tf32<INCH, HIDC><<<(Nn + 127) / 128, 256>>>(x, W1, Hlin);
    k_agg128<<<(Nn + 7) / 8, 256>>>(b1);

    // Layer 2: H2lin = Hagg @ W2 (tf32 -> bf16) ; Z = agg(H2lin) + b2 fp32
    gemm_tf32<HIDC, OUTC><<<(Nn + 127) / 128, 256>>>(Hagg, W2, H2lin);
    k_agg64<<<(Nn + 7) / 8, 256>>>(b2);

    // Scores
    k_score<<<(2 * EPp * 16 + 255) / 256, 256>>>(pose, nege, out);
}